// round 1
// baseline (speedup 1.0000x reference)
#include <cuda_runtime.h>
#include <cstdint>
#include <cstddef>

#define B   32
#define F   32
#define NP  1024
#define OC  32
#define K   8
#define TPB 256
#define PG  (NP / TPB)   // 4 point-groups per batch

typedef unsigned long long ull;

// ---- f32x2 packed helpers (sm_103a full-rate fp32 path) ----
__device__ __forceinline__ ull pack2(float lo, float hi) {
    ull r; asm("mov.b64 %0, {%1, %2};" : "=l"(r) : "f"(lo), "f"(hi)); return r;
}
__device__ __forceinline__ void unpack2(ull v, float& lo, float& hi) {
    asm("mov.b64 {%0, %1}, %2;" : "=f"(lo), "=f"(hi) : "l"(v));
}
#define FMA2(d, a, b) asm("fma.rn.f32x2 %0, %1, %2, %0;" : "+l"(d) : "l"(a), "l"(b))

// smem: shx[F][NP] | r[NP] | wsum[OC*F] | wdif[OC*F] | cvec[OC]
#define SMEM_FLOATS (F * NP + NP + OC * F + OC * F + OC)

extern "C" __global__ void __launch_bounds__(TPB, 1)
nla_kernel(const float* __restrict__ x, const float* __restrict__ mask,
           const float* __restrict__ Wd, const float* __restrict__ bd,
           const float* __restrict__ Ws, const float* __restrict__ bs,
           const float* __restrict__ bias, float* __restrict__ out)
{
    extern __shared__ float smem[];
    float* shx  = smem;                 // [F][NP]
    float* rsh  = smem + F * NP;        // [NP]
    float* wsum = rsh + NP;             // [OC*F]  (Wd + Ws)
    float* wdif = wsum + OC * F;        // [OC*F]
    float* cvec = wdif + OC * F;        // [OC]

    const int tid   = threadIdx.x;
    const int batch = blockIdx.x / PG;
    const int i     = (blockIdx.x % PG) * TPB + tid;   // point index in [0,NP)

    // ---- stage x[batch] (feature-major, contiguous) into smem via float4 ----
    {
        const float4* xg = (const float4*)(x + (size_t)batch * F * NP);
        float4* xs = (float4*)shx;
        #pragma unroll
        for (int t = 0; t < (F * NP / 4) / TPB; ++t)
            xs[tid + t * TPB] = xg[tid + t * TPB];
    }
    // ---- stage weights ----
    for (int t = tid; t < OC * F; t += TPB) {
        float wd = Wd[t];
        wdif[t] = wd;
        wsum[t] = wd + Ws[t];
    }
    if (tid < OC) cvec[tid] = bd[tid] + bs[tid] + bias[tid];
    __syncthreads();

    // ---- r[j] = sum_c x[c][j]^2 ----
    #pragma unroll
    for (int t = 0; t < NP / TPB; ++t) {
        int j = tid + t * TPB;
        float s = 0.f;
        #pragma unroll
        for (int c = 0; c < F; ++c) { float v = shx[c * NP + j]; s = fmaf(v, v, s); }
        rsh[j] = s;
    }
    __syncthreads();

    // ---- preload x_i as packed (v,v) pairs ----
    ull xi2[F];
    #pragma unroll
    for (int c = 0; c < F; ++c) { float v = shx[c * NP + i]; xi2[c] = pack2(v, v); }
    const float ri = rsh[i];

    // ---- top-8 state (value desc, index asc; strict > replicates lax.top_k ties) ----
    float tv[K]; int ti[K];
    #pragma unroll
    for (int t = 0; t < K; ++t) { tv[t] = -3.4e38f; ti[t] = 0; }

    const float4* mrow = (const float4*)(mask + (size_t)i * NP);

    // ---- main scan: 8 candidates per iteration, packed-f32x2 dot products ----
    for (int jb = 0; jb < NP; jb += 8) {
        ull a0 = 0ull, a1 = 0ull, a2 = 0ull, a3 = 0ull;  // packed (0.f, 0.f)
        #pragma unroll
        for (int c = 0; c < F; ++c) {
            ulonglong2 sA = *(const ulonglong2*)(shx + c * NP + jb);      // j..j+3
            ulonglong2 sB = *(const ulonglong2*)(shx + c * NP + jb + 4);  // j+4..j+7
            FMA2(a0, xi2[c], sA.x);
            FMA2(a1, xi2[c], sA.y);
            FMA2(a2, xi2[c], sB.x);
            FMA2(a3, xi2[c], sB.y);
        }
        float dot[8];
        unpack2(a0, dot[0], dot[1]); unpack2(a1, dot[2], dot[3]);
        unpack2(a2, dot[4], dot[5]); unpack2(a3, dot[6], dot[7]);

        float4 rr0 = *(const float4*)(rsh + jb);
        float4 rr1 = *(const float4*)(rsh + jb + 4);
        float rj[8] = {rr0.x, rr0.y, rr0.z, rr0.w, rr1.x, rr1.y, rr1.z, rr1.w};
        float4 m0 = __ldg(mrow + (jb >> 2));
        float4 m1 = __ldg(mrow + (jb >> 2) + 1);
        float mk[8] = {m0.x, m0.y, m0.z, m0.w, m1.x, m1.y, m1.z, m1.w};

        #pragma unroll
        for (int t = 0; t < 8; ++t) {
            // D = -(ri - 2*dot + rj); mask m in {0,1}: m*D + (m-1) -> exact -1 when masked
            float d = fmaf(2.f, dot[t], -(ri + rj[t]));
            float v = fmaf(mk[t], d, mk[t] - 1.f);
            if (v > tv[K - 1]) {            // strict: earlier index wins ties
                tv[K - 1] = v; ti[K - 1] = jb + t;
                #pragma unroll
                for (int s = K - 1; s > 0; --s) {
                    if (tv[s] > tv[s - 1]) {   // strict: stable among equals
                        float fv = tv[s]; tv[s] = tv[s - 1]; tv[s - 1] = fv;
                        int   fi = ti[s]; ti[s] = ti[s - 1]; ti[s - 1] = fi;
                    }
                }
            }
        }
    }

    // ---- mean of selected neighbors ----
    float m[F];
    #pragma unroll
    for (int c = 0; c < F; ++c) m[c] = 0.f;
    #pragma unroll
    for (int t = 0; t < K; ++t) {
        int j = ti[t];
        #pragma unroll
        for (int c = 0; c < F; ++c) m[c] += shx[c * NP + j];
    }
    const float invk = 1.f / (float)K;
    #pragma unroll
    for (int c = 0; c < F; ++c) m[c] *= invk;

    // ---- epilogue: out = xi @ (Wd+Ws)^T - m @ Wd^T + (bd+bs+bias) ----
    float xiv[F];
    #pragma unroll
    for (int c = 0; c < F; ++c) { float a, b2; unpack2(xi2[c], a, b2); xiv[c] = a; }

    float* ob = out + (size_t)batch * OC * NP + i;
    #pragma unroll
    for (int o = 0; o < OC; ++o) {
        float acc = cvec[o];
        #pragma unroll
        for (int c = 0; c < F; ++c) {
            acc = fmaf(xiv[c], wsum[o * F + c], acc);
            acc = fmaf(-m[c],  wdif[o * F + c], acc);
        }
        ob[o * NP] = acc;
    }
}

extern "C" void kernel_launch(void* const* d_in, const int* in_sizes, int n_in,
                              void* d_out, int out_size)
{
    (void)in_sizes; (void)n_in; (void)out_size;
    const float* x    = (const float*)d_in[0];
    const float* mask = (const float*)d_in[1];
    const float* Wd   = (const float*)d_in[2];
    const float* bd   = (const float*)d_in[3];
    const float* Ws   = (const float*)d_in[4];
    const float* bs   = (const float*)d_in[5];
    const float* bias = (const float*)d_in[6];
    // d_in[7] = k (fixed at 8 for this problem)

    cudaFuncSetAttribute(nla_kernel, cudaFuncAttributeMaxDynamicSharedMemorySize,
                         SMEM_FLOATS * (int)sizeof(float));

    nla_kernel<<<B * PG, TPB, SMEM_FLOATS * sizeof(float)>>>(
        x, mask, Wd, bd, Ws, bs, bias, (float*)d_out);
}

// round 2
// speedup vs baseline: 1.1087x; 1.1087x over previous
#include <cuda_runtime.h>
#include <cstdint>
#include <cstddef>

#define B   32
#define F   32
#define NP  1024
#define OC  32
#define K   8
#define TPB 256
#define PG  (NP / TPB)   // 4 point-groups per batch

typedef unsigned long long ull;

// ---- f32x2 packed helpers (sm_103a full-rate fp32 path) ----
__device__ __forceinline__ ull pack2(float lo, float hi) {
    ull r; asm("mov.b64 %0, {%1, %2};" : "=l"(r) : "f"(lo), "f"(hi)); return r;
}
__device__ __forceinline__ void unpack2(ull v, float& lo, float& hi) {
    asm("mov.b64 {%0, %1}, %2;" : "=f"(lo), "=f"(hi) : "l"(v));
}
#define FMA2_ACC(d, a, b) asm("fma.rn.f32x2 %0, %1, %2, %0;" : "+l"(d) : "l"(a), "l"(b))
__device__ __forceinline__ ull fma2(ull a, ull b, ull c) {
    ull d; asm("fma.rn.f32x2 %0, %1, %2, %3;" : "=l"(d) : "l"(a), "l"(b), "l"(c)); return d;
}
__device__ __forceinline__ ull add2(ull a, ull b) {
    ull d; asm("add.rn.f32x2 %0, %1, %2;" : "=l"(d) : "l"(a), "l"(b)); return d;
}

// smem: shx[F][NP] | r[NP] | wsum[OC*F] | wdif[OC*F] | cvec[OC]
#define SMEM_FLOATS (F * NP + NP + OC * F + OC * F + OC)

extern "C" __global__ void __launch_bounds__(TPB, 1)
nla_kernel(const float* __restrict__ x, const float* __restrict__ mask,
           const float* __restrict__ Wd, const float* __restrict__ bd,
           const float* __restrict__ Ws, const float* __restrict__ bs,
           const float* __restrict__ bias, float* __restrict__ out)
{
    extern __shared__ float smem[];
    float* shx  = smem;                 // [F][NP]
    float* rsh  = smem + F * NP;        // [NP]
    float* wsum = rsh + NP;             // [OC*F]  (Wd + Ws)
    float* wdif = wsum + OC * F;        // [OC*F]
    float* cvec = wdif + OC * F;        // [OC]

    const int tid   = threadIdx.x;
    const int batch = blockIdx.x / PG;
    const int i     = (blockIdx.x % PG) * TPB + tid;   // point index in [0,NP)

    // ---- stage x[batch] (feature-major, contiguous) into smem via float4 ----
    {
        const float4* xg = (const float4*)(x + (size_t)batch * F * NP);
        float4* xs = (float4*)shx;
        #pragma unroll
        for (int t = 0; t < (F * NP / 4) / TPB; ++t)
            xs[tid + t * TPB] = xg[tid + t * TPB];
    }
    // ---- stage weights ----
    for (int t = tid; t < OC * F; t += TPB) {
        float wd = Wd[t];
        wdif[t] = wd;
        wsum[t] = wd + Ws[t];
    }
    if (tid < OC) cvec[tid] = bd[tid] + bs[tid] + bias[tid];
    __syncthreads();

    // ---- r[j] = sum_c x[c][j]^2 ----
    #pragma unroll
    for (int t = 0; t < NP / TPB; ++t) {
        int j = tid + t * TPB;
        float s = 0.f;
        #pragma unroll
        for (int c = 0; c < F; ++c) { float v = shx[c * NP + j]; s = fmaf(v, v, s); }
        rsh[j] = s;
    }
    __syncthreads();

    // ---- preload x_i as packed (v,v) pairs ----
    ull xi2[F];
    #pragma unroll
    for (int c = 0; c < F; ++c) { float v = shx[c * NP + i]; xi2[c] = pack2(v, v); }
    const float ri = rsh[i];

    const ull two2  = pack2(2.f, 2.f);
    const ull neg12 = pack2(-1.f, -1.f);
    const ull nri2  = pack2(-ri, -ri);

    // ---- top-8 state (value desc; strict > keeps earliest-scanned among ties,
    //      which with the window-first ascending scan == smallest index,
    //      matching lax.top_k) ----
    float tv[K]; int ti[K];
    #pragma unroll
    for (int t = 0; t < K; ++t) { tv[t] = -3.4e38f; ti[t] = 0; }

    const float* mrow = mask + (size_t)i * NP;

    // Scan start: just before this warp's local mask window (masked entries
    // for lane i lie in [i-33, i+33]); window indices are then visited in
    // ascending index order, so tv[7] hits the -1 tie plateau after ~9 blocks.
    const int warpbase = (blockIdx.x % PG) * TPB + (tid & ~31);
    const int jb0 = (warpbase - 40 + NP) & (NP - 1);   // 8-aligned, warp-uniform

    for (int t = 0; t < NP / 8; ++t) {
        const int jj = (jb0 + t * 8) & (NP - 1);
        const float* xb = shx + jj;

        ull a0 = 0ull, a1 = 0ull, a2 = 0ull, a3 = 0ull;  // packed (0,0)
        #pragma unroll
        for (int c = 0; c < F; ++c) {
            ulonglong2 sA = *(const ulonglong2*)(xb + c * NP);      // j..j+3
            ulonglong2 sB = *(const ulonglong2*)(xb + c * NP + 4);  // j+4..j+7
            FMA2_ACC(a0, xi2[c], sA.x);
            FMA2_ACC(a1, xi2[c], sA.y);
            FMA2_ACC(a2, xi2[c], sB.x);
            FMA2_ACC(a3, xi2[c], sB.y);
        }

        // packed: v = m * (2*dot - ri - rj) + (m - 1); exact -1 when masked
        ulonglong2 rA = *(const ulonglong2*)(rsh + jj);
        ulonglong2 rB = *(const ulonglong2*)(rsh + jj + 4);
        ulonglong2 mA = *(const ulonglong2*)(mrow + jj);
        ulonglong2 mB = *(const ulonglong2*)(mrow + jj + 4);

        ull d0 = fma2(a0, two2, fma2(rA.x, neg12, nri2));
        ull d1 = fma2(a1, two2, fma2(rA.y, neg12, nri2));
        ull d2 = fma2(a2, two2, fma2(rB.x, neg12, nri2));
        ull d3 = fma2(a3, two2, fma2(rB.y, neg12, nri2));
        ull v0 = fma2(mA.x, d0, add2(mA.x, neg12));
        ull v1 = fma2(mA.y, d1, add2(mA.y, neg12));
        ull v2 = fma2(mB.x, d2, add2(mB.x, neg12));
        ull v3 = fma2(mB.y, d3, add2(mB.y, neg12));

        float v[8];
        unpack2(v0, v[0], v[1]); unpack2(v1, v[2], v[3]);
        unpack2(v2, v[4], v[5]); unpack2(v3, v[6], v[7]);

        // block-max prefilter: one branch per 8 candidates (FMNMX -> alu pipe)
        float bm = fmaxf(fmaxf(fmaxf(v[0], v[1]), fmaxf(v[2], v[3])),
                         fmaxf(fmaxf(v[4], v[5]), fmaxf(v[6], v[7])));
        if (bm > tv[K - 1]) {
            #pragma unroll
            for (int u = 0; u < 8; ++u) {
                if (v[u] > tv[K - 1]) {        // strict: earlier-scanned wins ties
                    tv[K - 1] = v[u]; ti[K - 1] = jj + u;
                    #pragma unroll
                    for (int s = K - 1; s > 0; --s) {
                        if (tv[s] > tv[s - 1]) {
                            float fv = tv[s]; tv[s] = tv[s - 1]; tv[s - 1] = fv;
                            int   fi = ti[s]; ti[s] = ti[s - 1]; ti[s - 1] = fi;
                        }
                    }
                }
            }
        }
    }

    // ---- mean of selected neighbors (set is order-invariant) ----
    float m[F];
    #pragma unroll
    for (int c = 0; c < F; ++c) m[c] = 0.f;
    #pragma unroll
    for (int t = 0; t < K; ++t) {
        int j = ti[t];
        #pragma unroll
        for (int c = 0; c < F; ++c) m[c] += shx[c * NP + j];
    }
    const float invk = 1.f / (float)K;
    #pragma unroll
    for (int c = 0; c < F; ++c) m[c] *= invk;

    // ---- epilogue: out = xi @ (Wd+Ws)^T - m @ Wd^T + (bd+bs+bias) ----
    float xiv[F];
    #pragma unroll
    for (int c = 0; c < F; ++c) { float a, b2; unpack2(xi2[c], a, b2); xiv[c] = a; }

    float* ob = out + (size_t)batch * OC * NP + i;
    #pragma unroll
    for (int o = 0; o < OC; ++o) {
        float acc = cvec[o];
        #pragma unroll
        for (int c = 0; c < F; ++c) {
            acc = fmaf(xiv[c], wsum[o * F + c], acc);
            acc = fmaf(-m[c],  wdif[o * F + c], acc);
        }
        ob[o * NP] = acc;
    }
}

extern "C" void kernel_launch(void* const* d_in, const int* in_sizes, int n_in,
                              void* d_out, int out_size)
{
    (void)in_sizes; (void)n_in; (void)out_size;
    const float* x    = (const float*)d_in[0];
    const float* mask = (const float*)d_in[1];
    const float* Wd   = (const float*)d_in[2];
    const float* bd   = (const float*)d_in[3];
    const float* Ws   = (const float*)d_in[4];
    const float* bs   = (const float*)d_in[5];
    const float* bias = (const float*)d_in[6];
    // d_in[7] = k (fixed at 8 for this problem)

    cudaFuncSetAttribute(nla_kernel, cudaFuncAttributeMaxDynamicSharedMemorySize,
                         SMEM_FLOATS * (int)sizeof(float));

    nla_kernel<<<B * PG, TPB, SMEM_FLOATS * sizeof(float)>>>(
        x, mask, Wd, bd, Ws, bs, bias, (float*)d_out);
}